// round 4
// baseline (speedup 1.0000x reference)
#include <cuda_runtime.h>
#include <cstdint>

#define EPS 1e-5f

// ---------------- scratch (device globals; allocation-free) ----------------
__device__ float g_u12red[32 * 1024];       // [r, ii]  sum over last axis of U12
__device__ float g_u3red [32 * 1024];       // [r, jj]  sum over last axis of U3R
__device__ float g_remb[64 * 32];           // BN(R[r_idx])
__device__ float g_e2  [64 * 32];           // BN(E[e2_idx])
__device__ float g_e3  [64 * 32];           // BN(E[e3_idx])
__device__ float g_a   [64 * 32];           // U_root[r_idx].sum(-1)  [b][r]
__device__ float g_p   [32];                // P.sum(-1)
__device__ float g_vec_part[32 * 2048];     // per-r partial of vec [r][b*32+k]
__device__ float g_vecn[64 * 32];           // BN(vec)
__device__ float g_bsum[256 * 64];          // per-logit-block exp partial sums

static const int NBLK_LOG = (50000 + 255) / 256;   // 196

// ---------------- K1: row reduction of U12 and U3R (the 256 MB stream) -----
__global__ void reduce_kernel(const float* __restrict__ U12,
                              const float* __restrict__ U3R)
{
    int gw   = (blockIdx.x * 256 + threadIdx.x) >> 5;   // global warp id, 65536 total
    int lane = threadIdx.x & 31;
    const float* src;
    float* dst;
    int row;
    if (gw < 32768) { src = U12; dst = g_u12red; row = gw; }
    else            { src = U3R; dst = g_u3red;  row = gw - 32768; }

    const float4* p = reinterpret_cast<const float4*>(src + (size_t)row * 1024) + lane;
    float4 a0 = p[0],   a1 = p[32],  a2 = p[64],  a3 = p[96];
    float4 a4 = p[128], a5 = p[160], a6 = p[192], a7 = p[224];
    float s = ((a0.x + a0.y) + (a0.z + a0.w)) + ((a1.x + a1.y) + (a1.z + a1.w))
            + ((a2.x + a2.y) + (a2.z + a2.w)) + ((a3.x + a3.y) + (a3.z + a3.w))
            + ((a4.x + a4.y) + (a4.z + a4.w)) + ((a5.x + a5.y) + (a5.z + a5.w))
            + ((a6.x + a6.y) + (a6.z + a6.w)) + ((a7.x + a7.y) + (a7.z + a7.w));
    #pragma unroll
    for (int off = 16; off; off >>= 1)
        s += __shfl_down_sync(0xffffffffu, s, off);
    if (lane == 0) dst[row] = s;
}

// ---------------- K2: gathers, BatchNorms, small row-sums ------------------
__global__ void prep_kernel(const float* __restrict__ E,
                            const float* __restrict__ R,
                            const float* __restrict__ U_root,
                            const float* __restrict__ P,
                            const float* __restrict__ gr, const float* __restrict__ br,
                            const float* __restrict__ ge, const float* __restrict__ be,
                            const int* __restrict__ r_idx,
                            const int* __restrict__ e2_idx,
                            const int* __restrict__ e3_idx)
{
    __shared__ float sh[2048];
    __shared__ int ridx[64], e2i[64], e3i[64];
    int t = threadIdx.x;
    if (t < 64) { ridx[t] = r_idx[t]; e2i[t] = e2_idx[t]; e3i[t] = e3_idx[t]; }
    __syncthreads();

    // ---- r_emb = BN(R[r_idx]) ----
    for (int i = t; i < 2048; i += 256)
        sh[i] = R[(size_t)ridx[i >> 5] * 32 + (i & 31)];
    __syncthreads();
    if (t < 32) {
        float m = 0.f;
        for (int b = 0; b < 64; b++) m += sh[b * 32 + t];
        m *= (1.f / 64.f);
        float v = 0.f;
        for (int b = 0; b < 64; b++) { float d = sh[b * 32 + t] - m; v += d * d; }
        v *= (1.f / 64.f);
        float sc = gr[t] * rsqrtf(v + EPS);
        float of = br[t] - m * sc;
        for (int b = 0; b < 64; b++) g_remb[b * 32 + t] = sh[b * 32 + t] * sc + of;
    }
    __syncthreads();

    // ---- e2 = BN(E[e2_idx]) ----
    for (int i = t; i < 2048; i += 256)
        sh[i] = E[(size_t)e2i[i >> 5] * 32 + (i & 31)];
    __syncthreads();
    if (t < 32) {
        float m = 0.f;
        for (int b = 0; b < 64; b++) m += sh[b * 32 + t];
        m *= (1.f / 64.f);
        float v = 0.f;
        for (int b = 0; b < 64; b++) { float d = sh[b * 32 + t] - m; v += d * d; }
        v *= (1.f / 64.f);
        float sc = ge[t] * rsqrtf(v + EPS);
        float of = be[t] - m * sc;
        for (int b = 0; b < 64; b++) g_e2[b * 32 + t] = sh[b * 32 + t] * sc + of;
    }
    __syncthreads();

    // ---- e3 = BN(E[e3_idx]) ----
    for (int i = t; i < 2048; i += 256)
        sh[i] = E[(size_t)e3i[i >> 5] * 32 + (i & 31)];
    __syncthreads();
    if (t < 32) {
        float m = 0.f;
        for (int b = 0; b < 64; b++) m += sh[b * 32 + t];
        m *= (1.f / 64.f);
        float v = 0.f;
        for (int b = 0; b < 64; b++) { float d = sh[b * 32 + t] - m; v += d * d; }
        v *= (1.f / 64.f);
        float sc = ge[t] * rsqrtf(v + EPS);
        float of = be[t] - m * sc;
        for (int b = 0; b < 64; b++) g_e3[b * 32 + t] = sh[b * 32 + t] * sc + of;
    }

    // ---- a[b][r] = U_root[r_idx[b]].sum(-1) ----
    for (int i = t; i < 2048; i += 256) {
        int b = i >> 5, r = i & 31;
        const float* row = U_root + ((size_t)ridx[b] * 32 + r) * 32;
        float s = 0.f;
        #pragma unroll
        for (int k = 0; k < 32; k++) s += row[k];
        g_a[i] = s;
    }
    // ---- p[r] = P.sum(-1) ----
    if (t < 32) {
        const float* row = P + t * 32;
        float s = 0.f;
        #pragma unroll
        for (int k = 0; k < 32; k++) s += row[k];
        g_p[t] = s;
    }
}

// ---------------- K3: per-rank contraction --------------------------------
__global__ void per_r_kernel(const int* __restrict__ miss_p)
{
    int r = blockIdx.x, t = threadIdx.x;
    __shared__ float u12row[1024], u3row[1024];
    __shared__ float remb[64][33], e2s[64][33], e3s[64][33];
    __shared__ float w[64];
    int miss = miss_p ? *miss_p : 3;

    for (int i = t; i < 1024; i += 256) {
        u12row[i] = g_u12red[r * 1024 + i];
        u3row[i]  = g_u3red [r * 1024 + i];
    }
    for (int i = t; i < 2048; i += 256) {
        int b = i >> 5, d = i & 31;
        remb[b][d] = g_remb[i];
        e2s[b][d]  = g_e2[i];
        e3s[b][d]  = g_e3[i];
    }
    __syncthreads();

    // per-b scalar (s2 for miss 2/3, q for miss 1), 4 threads per b
    {
        int b = t >> 2, part = t & 3;
        const float* urow = (miss == 1) ? u3row : u12row;
        const float* hi   = (miss == 1) ? &e2s[b][0] : &remb[b][0];
        const float* lo   = (miss == 1) ? &e3s[b][0] : &e2s[b][0];
        float s = 0.f;
        #pragma unroll 4
        for (int it = 0; it < 256; it++) {
            int jj = it * 4 + part;
            s += urow[jj] * hi[jj >> 5] * lo[jj & 31];
        }
        s += __shfl_down_sync(0xffffffffu, s, 2, 4);
        s += __shfl_down_sync(0xffffffffu, s, 1, 4);
        if (part == 0) w[b] = s * g_a[b * 32 + r] * g_p[r];
    }
    __syncthreads();

    // vec contribution per (b, out)
    for (int i = t; i < 2048; i += 256) {
        int b = i >> 5, o = i & 31;
        float acc = 0.f;
        if (miss == 1) {
            #pragma unroll
            for (int d = 0; d < 32; d++) acc += remb[b][d] * u12row[d * 32 + o];
        } else if (miss == 2) {
            #pragma unroll
            for (int k = 0; k < 32; k++) acc += e3s[b][k] * u3row[o * 32 + k];
        } else {
            #pragma unroll
            for (int j = 0; j < 32; j++) acc += e3s[b][j] * u3row[j * 32 + o];
        }
        g_vec_part[r * 2048 + i] = acc * w[b];
    }
}

// ---------------- K4: reduce partials over r, BN(vec) ----------------------
__global__ void bn_vec_kernel(const float* __restrict__ gw, const float* __restrict__ bw)
{
    __shared__ float v[2048];
    int t = threadIdx.x;
    for (int i = t; i < 2048; i += 256) {
        float s = 0.f;
        #pragma unroll
        for (int r = 0; r < 32; r++) s += g_vec_part[r * 2048 + i];
        v[i] = s;
    }
    __syncthreads();
    if (t < 32) {
        float m = 0.f;
        for (int b = 0; b < 64; b++) m += v[b * 32 + t];
        m *= (1.f / 64.f);
        float var = 0.f;
        for (int b = 0; b < 64; b++) { float d = v[b * 32 + t] - m; var += d * d; }
        var *= (1.f / 64.f);
        float sc = gw[t] * rsqrtf(var + EPS);
        float of = bw[t] - m * sc;
        for (int b = 0; b < 64; b++) g_vecn[b * 32 + t] = v[b * 32 + t] * sc + of;
    }
}

// ---------------- K5: logits + exp + per-block sums ------------------------
__global__ void logits_kernel(const float* __restrict__ E, float* __restrict__ out)
{
    __shared__ float vecn[2048];
    __shared__ float wsum[64][8];
    int t = threadIdx.x;
    for (int i = t; i < 2048; i += 256) vecn[i] = g_vecn[i];
    __syncthreads();

    int n = blockIdx.x * 256 + t;
    bool valid = n < 50000;
    float er[32];
    if (valid) {
        const float4* p = reinterpret_cast<const float4*>(E + (size_t)n * 32);
        #pragma unroll
        for (int q = 0; q < 8; q++) {
            float4 v = p[q];
            er[q * 4 + 0] = v.x; er[q * 4 + 1] = v.y;
            er[q * 4 + 2] = v.z; er[q * 4 + 3] = v.w;
        }
    } else {
        #pragma unroll
        for (int q = 0; q < 32; q++) er[q] = 0.f;
    }

    int wid = t >> 5, lane = t & 31;
    for (int b = 0; b < 64; b++) {
        float l = 0.f;
        #pragma unroll
        for (int k = 0; k < 32; k++) l += vecn[b * 32 + k] * er[k];
        float pv = valid ? __expf(l) : 0.f;
        if (valid) out[(size_t)b * 50000 + n] = pv;
        #pragma unroll
        for (int off = 16; off; off >>= 1)
            pv += __shfl_down_sync(0xffffffffu, pv, off);
        if (lane == 0) wsum[b][wid] = pv;
    }
    __syncthreads();
    if (t < 64) {
        float s = 0.f;
        #pragma unroll
        for (int wdx = 0; wdx < 8; wdx++) s += wsum[t][wdx];
        g_bsum[blockIdx.x * 64 + t] = s;
    }
}

// ---------------- K6: normalize --------------------------------------------
__global__ void norm_kernel(float* __restrict__ out, int nblk)
{
    __shared__ float red[256];
    __shared__ float inv;
    int b = blockIdx.y;
    int t = threadIdx.x;
    float s = 0.f;
    if (t < nblk) s = g_bsum[t * 64 + b];
    red[t] = s;
    __syncthreads();
    #pragma unroll
    for (int off = 128; off; off >>= 1) {
        if (t < off) red[t] += red[t + off];
        __syncthreads();
    }
    if (t == 0) inv = 1.f / red[0];
    __syncthreads();

    int i = blockIdx.x * 256 + t;   // float4 index within row (12500 per row)
    if (i < 12500) {
        float4* p = reinterpret_cast<float4*>(out + (size_t)b * 50000);
        float4 v = p[i];
        v.x *= inv; v.y *= inv; v.z *= inv; v.w *= inv;
        p[i] = v;
    }
}

// ---------------- launch ----------------------------------------------------
extern "C" void kernel_launch(void* const* d_in, const int* in_sizes, int n_in,
                              void* d_out, int out_size)
{
    const float* E      = (const float*)d_in[0];
    const float* R      = (const float*)d_in[1];
    const float* U_root = (const float*)d_in[2];
    const float* U12    = (const float*)d_in[3];
    const float* U3R    = (const float*)d_in[4];
    const float* P      = (const float*)d_in[5];
    const float* gr     = (const float*)d_in[6];
    const float* br     = (const float*)d_in[7];
    const float* ge     = (const float*)d_in[8];
    const float* be     = (const float*)d_in[9];
    const float* gw     = (const float*)d_in[10];
    const float* bw     = (const float*)d_in[11];
    const int* r_idx    = (const int*)d_in[12];
    const int* e2_idx   = (const int*)d_in[13];
    const int* e3_idx   = (const int*)d_in[14];
    const int* miss     = (n_in > 15) ? (const int*)d_in[15] : nullptr;
    float* out = (float*)d_out;

    reduce_kernel<<<8192, 256>>>(U12, U3R);
    prep_kernel<<<1, 256>>>(E, R, U_root, P, gr, br, ge, be, r_idx, e2_idx, e3_idx);
    per_r_kernel<<<32, 256>>>(miss);
    bn_vec_kernel<<<1, 256>>>(gw, bw);
    logits_kernel<<<NBLK_LOG, 256>>>(E, out);
    norm_kernel<<<dim3((12500 + 255) / 256, 64), 256>>>(out, NBLK_LOG);
}

// round 5
// speedup vs baseline: 1.4848x; 1.4848x over previous
#include <cuda_runtime.h>
#include <cstdint>

#define EPS 1e-5f

// ---------------- scratch (device globals; allocation-free) ----------------
__device__ float g_u12red[32 * 1024];       // [r, ii]  sum over last axis of U12
__device__ float g_u3red [32 * 1024];       // [r, jj]  sum over last axis of U3R
__device__ float g_remb[64 * 32];           // BN(R[r_idx])
__device__ float g_e2  [64 * 32];           // BN(E[e2_idx])
__device__ float g_e3  [64 * 32];           // BN(E[e3_idx])
__device__ float g_a   [64 * 32];           // U_root[r_idx].sum(-1)  [b][r]
__device__ float g_p   [32];                // P.sum(-1)
__device__ float g_vec [64 * 32];           // vec (pre-BN)
__device__ float g_bsum[256 * 64];          // per-logit-block exp partial sums
__device__ float g_inv [64];                // 1 / softmax denom per b

static const int NBLK_LOG = (50000 + 255) / 256;   // 196

// ---------------- K1: row reduction of U12 and U3R (the 256 MB stream) -----
__global__ void reduce_kernel(const float* __restrict__ U12,
                              const float* __restrict__ U3R)
{
    int gw   = (blockIdx.x * 256 + threadIdx.x) >> 5;   // global warp id, 65536 total
    int lane = threadIdx.x & 31;
    const float* src;
    float* dst;
    int row;
    if (gw < 32768) { src = U12; dst = g_u12red; row = gw; }
    else            { src = U3R; dst = g_u3red;  row = gw - 32768; }

    const float4* p = reinterpret_cast<const float4*>(src + (size_t)row * 1024) + lane;
    float4 a0 = p[0],   a1 = p[32],  a2 = p[64],  a3 = p[96];
    float4 a4 = p[128], a5 = p[160], a6 = p[192], a7 = p[224];
    float s = ((a0.x + a0.y) + (a0.z + a0.w)) + ((a1.x + a1.y) + (a1.z + a1.w))
            + ((a2.x + a2.y) + (a2.z + a2.w)) + ((a3.x + a3.y) + (a3.z + a3.w))
            + ((a4.x + a4.y) + (a4.z + a4.w)) + ((a5.x + a5.y) + (a5.z + a5.w))
            + ((a6.x + a6.y) + (a6.z + a6.w)) + ((a7.x + a7.y) + (a7.z + a7.w));
    #pragma unroll
    for (int off = 16; off; off >>= 1)
        s += __shfl_down_sync(0xffffffffu, s, off);
    if (lane == 0) dst[row] = s;
}

// ---------------- helper: BN over 64 rows of 32 features in shared ---------
__device__ __forceinline__ void bn_store(const float* sh, const float* g,
                                         const float* bsh, float* dst, int t)
{
    if (t < 32) {
        float m = 0.f;
        #pragma unroll 8
        for (int b = 0; b < 64; b++) m += sh[b * 32 + t];
        m *= (1.f / 64.f);
        float v = 0.f;
        #pragma unroll 8
        for (int b = 0; b < 64; b++) { float d = sh[b * 32 + t] - m; v += d * d; }
        v *= (1.f / 64.f);
        float sc = g[t] * rsqrtf(v + EPS);
        float of = bsh[t] - m * sc;
        #pragma unroll 8
        for (int b = 0; b < 64; b++) dst[b * 32 + t] = sh[b * 32 + t] * sc + of;
    }
}

// ---------------- K2: gathers, BatchNorms, small row-sums ------------------
__global__ void prep_kernel(const float* __restrict__ E,
                            const float* __restrict__ R,
                            const float* __restrict__ U_root,
                            const float* __restrict__ P,
                            const float* __restrict__ gr, const float* __restrict__ br,
                            const float* __restrict__ ge, const float* __restrict__ be,
                            const int* __restrict__ r_idx,
                            const int* __restrict__ e2_idx,
                            const int* __restrict__ e3_idx)
{
    __shared__ float shr[2048], sh2[2048], sh3[2048];
    __shared__ int ridx[64], e2i[64], e3i[64];
    int t = threadIdx.x;                     // 1024 threads
    if (t < 64)            ridx[t]       = r_idx[t];
    else if (t < 128)      e2i[t - 64]   = e2_idx[t - 64];
    else if (t < 192)      e3i[t - 128]  = e3_idx[t - 128];
    __syncthreads();

    for (int i = t; i < 2048; i += 1024) {
        int b = i >> 5, d = i & 31;
        shr[i] = R[(size_t)ridx[b] * 32 + d];
        sh2[i] = E[(size_t)e2i[b] * 32 + d];
        sh3[i] = E[(size_t)e3i[b] * 32 + d];
    }
    __syncthreads();

    bn_store(shr, gr, br, g_remb, t);
    bn_store(sh2, ge, be, g_e2, t);
    bn_store(sh3, ge, be, g_e3, t);

    // a[b][r] = U_root[r_idx[b]].sum(-1)
    for (int i = t; i < 2048; i += 1024) {
        int b = i >> 5, r = i & 31;
        const float4* row = reinterpret_cast<const float4*>(
            U_root + ((size_t)ridx[b] * 32 + r) * 32);
        float4 v0 = row[0], v1 = row[1], v2 = row[2], v3 = row[3];
        float4 v4 = row[4], v5 = row[5], v6 = row[6], v7 = row[7];
        g_a[i] = ((v0.x+v0.y)+(v0.z+v0.w)) + ((v1.x+v1.y)+(v1.z+v1.w))
               + ((v2.x+v2.y)+(v2.z+v2.w)) + ((v3.x+v3.y)+(v3.z+v3.w))
               + ((v4.x+v4.y)+(v4.z+v4.w)) + ((v5.x+v5.y)+(v5.z+v5.w))
               + ((v6.x+v6.y)+(v6.z+v6.w)) + ((v7.x+v7.y)+(v7.z+v7.w));
    }
    // p[r] = P.sum(-1)
    if (t >= 992) {                          // last warp
        int r = t - 992;
        const float4* row = reinterpret_cast<const float4*>(P + r * 32);
        float s = 0.f;
        #pragma unroll
        for (int q = 0; q < 8; q++) { float4 v = row[q]; s += (v.x+v.y)+(v.z+v.w); }
        g_p[r] = s;
    }
}

// ---------------- K3: per-batch contraction (64 blocks, 1 per b) -----------
__global__ void contract_kernel(const int* __restrict__ miss_p)
{
    int b = blockIdx.x, t = threadIdx.x;
    int wid = t >> 5, lane = t & 31;
    int miss = miss_p ? *miss_p : 3;

    __shared__ float A1s[32], A2s[32], Vs[32];
    __shared__ float m[1024];                // outer product A1⊗A2
    __shared__ float y[1024];                // coef[r]*V[j]
    __shared__ float coef[32];
    __shared__ float partial[8][32];

    if (t < 32) {
        if (miss == 1) { A1s[t] = g_e2[b*32+t];  A2s[t] = g_e3[b*32+t]; Vs[t] = g_remb[b*32+t]; }
        else           { A1s[t] = g_remb[b*32+t]; A2s[t] = g_e2[b*32+t]; Vs[t] = g_e3[b*32+t]; }
    }
    __syncthreads();
    for (int i = t; i < 1024; i += 256) m[i] = A1s[i >> 5] * A2s[i & 31];
    __syncthreads();

    const float* SU = (miss == 1) ? g_u3red  : g_u12red;   // scalar side
    const float* TU = (miss == 1) ? g_u12red : g_u3red;    // vector side

    // coef[r] = (Σ_ii SU[r,ii]*m[ii]) * a[b,r] * p[r]; warp wid owns r in [4w,4w+4)
    #pragma unroll
    for (int rr = 0; rr < 4; rr++) {
        int r = wid * 4 + rr;
        const float4* row = reinterpret_cast<const float4*>(SU + (size_t)r * 1024);
        float s = 0.f;
        #pragma unroll
        for (int q = 0; q < 8; q++) {
            float4 u = row[q * 32 + lane];
            const float4 mm = reinterpret_cast<const float4*>(m)[q * 32 + lane];
            s += u.x * mm.x + u.y * mm.y + u.z * mm.z + u.w * mm.w;
        }
        #pragma unroll
        for (int off = 16; off; off >>= 1)
            s += __shfl_down_sync(0xffffffffu, s, off);
        if (lane == 0) coef[r] = s * g_a[b * 32 + r] * g_p[r];
    }
    __syncthreads();
    for (int i = t; i < 1024; i += 256) y[i] = coef[i >> 5] * Vs[i & 31];
    __syncthreads();

    // output: thread (k=t&31, part=t>>5); part owns r in [4p,4p+4)
    int k = t & 31, part = t >> 5;
    float acc = 0.f;
    if (miss == 2) {
        // vec[o] = Σ_{r,kk} y[r*32+kk] * TU[r, o*32+kk]   (out-first)
        #pragma unroll
        for (int rr = 0; rr < 4; rr++) {
            int r = part * 4 + rr;
            const float4* seg = reinterpret_cast<const float4*>(TU + (size_t)r * 1024 + k * 32);
            #pragma unroll
            for (int q = 0; q < 8; q++) {
                float4 u = seg[q];
                acc += u.x * y[r*32 + q*4]   + u.y * y[r*32 + q*4+1]
                     + u.z * y[r*32 + q*4+2] + u.w * y[r*32 + q*4+3];
            }
        }
    } else {
        // vec[k] = Σ_{r,j} y[r*32+j] * TU[r, j*32+k]      (sum-first)
        #pragma unroll
        for (int rr = 0; rr < 4; rr++) {
            int r = part * 4 + rr;
            #pragma unroll
            for (int j = 0; j < 32; j++)
                acc += y[r * 32 + j] * TU[(size_t)r * 1024 + j * 32 + k];
        }
    }
    partial[part][k] = acc;
    __syncthreads();
    if (t < 32) {
        float s = 0.f;
        #pragma unroll
        for (int p8 = 0; p8 < 8; p8++) s += partial[p8][t];
        g_vec[b * 32 + t] = s;
    }
}

// ---------------- K4: logits + exp + per-block sums (BN(vec) inline) -------
__global__ void logits_kernel(const float* __restrict__ E,
                              const float* __restrict__ gw,
                              const float* __restrict__ bw,
                              float* __restrict__ out)
{
    __shared__ float4 vecn4[512];            // BN'd vec, [b][8] float4
    __shared__ float  vraw[2048];
    __shared__ float  wsum[64][8];
    int t = threadIdx.x;
    for (int i = t; i < 2048; i += 256) vraw[i] = g_vec[i];
    __syncthreads();
    if (t < 32) {                            // per-feature BN (redundant per block, deterministic)
        float m = 0.f;
        #pragma unroll 8
        for (int b = 0; b < 64; b++) m += vraw[b * 32 + t];
        m *= (1.f / 64.f);
        float v = 0.f;
        #pragma unroll 8
        for (int b = 0; b < 64; b++) { float d = vraw[b * 32 + t] - m; v += d * d; }
        v *= (1.f / 64.f);
        float sc = gw[t] * rsqrtf(v + EPS);
        float of = bw[t] - m * sc;
        #pragma unroll 8
        for (int b = 0; b < 64; b++)
            reinterpret_cast<float*>(vecn4)[b * 32 + t] = vraw[b * 32 + t] * sc + of;
    }
    __syncthreads();

    int n = blockIdx.x * 256 + t;
    bool valid = n < 50000;
    float4 er4[8];
    if (valid) {
        const float4* p = reinterpret_cast<const float4*>(E + (size_t)n * 32);
        #pragma unroll
        for (int q = 0; q < 8; q++) er4[q] = p[q];
    } else {
        #pragma unroll
        for (int q = 0; q < 8; q++) er4[q] = make_float4(0.f, 0.f, 0.f, 0.f);
    }

    int wid = t >> 5, lane = t & 31;
    for (int b = 0; b < 64; b += 4) {
        float l0 = 0.f, l1 = 0.f, l2 = 0.f, l3 = 0.f;
        #pragma unroll
        for (int q = 0; q < 8; q++) {
            float4 e = er4[q];
            float4 v0 = vecn4[(b+0)*8 + q];
            float4 v1 = vecn4[(b+1)*8 + q];
            float4 v2 = vecn4[(b+2)*8 + q];
            float4 v3 = vecn4[(b+3)*8 + q];
            l0 += v0.x*e.x + v0.y*e.y + v0.z*e.z + v0.w*e.w;
            l1 += v1.x*e.x + v1.y*e.y + v1.z*e.z + v1.w*e.w;
            l2 += v2.x*e.x + v2.y*e.y + v2.z*e.z + v2.w*e.w;
            l3 += v3.x*e.x + v3.y*e.y + v3.z*e.z + v3.w*e.w;
        }
        float p0 = valid ? __expf(l0) : 0.f;
        float p1 = valid ? __expf(l1) : 0.f;
        float p2 = valid ? __expf(l2) : 0.f;
        float p3 = valid ? __expf(l3) : 0.f;
        if (valid) {
            out[(size_t)(b+0) * 50000 + n] = p0;
            out[(size_t)(b+1) * 50000 + n] = p1;
            out[(size_t)(b+2) * 50000 + n] = p2;
            out[(size_t)(b+3) * 50000 + n] = p3;
        }
        #pragma unroll
        for (int off = 16; off; off >>= 1) {   // 4 interleaved butterflies
            p0 += __shfl_down_sync(0xffffffffu, p0, off);
            p1 += __shfl_down_sync(0xffffffffu, p1, off);
            p2 += __shfl_down_sync(0xffffffffu, p2, off);
            p3 += __shfl_down_sync(0xffffffffu, p3, off);
        }
        if (lane == 0) {
            wsum[b+0][wid] = p0; wsum[b+1][wid] = p1;
            wsum[b+2][wid] = p2; wsum[b+3][wid] = p3;
        }
    }
    __syncthreads();
    if (t < 64) {
        float s = 0.f;
        #pragma unroll
        for (int w8 = 0; w8 < 8; w8++) s += wsum[t][w8];
        g_bsum[blockIdx.x * 64 + t] = s;
    }
}

// ---------------- K5: per-b denominators (once) -----------------------------
__global__ void suminv_kernel(int nblk)
{
    __shared__ float part[4][64];
    int t = threadIdx.x;                     // 256
    int b = t & 63, p = t >> 6;              // 4 partitions of blocks
    float s = 0.f;
    for (int q = p; q < nblk; q += 4)
        s += g_bsum[q * 64 + b];
    part[p][b] = s;
    __syncthreads();
    if (t < 64) {
        float tot = part[0][t] + part[1][t] + part[2][t] + part[3][t];
        g_inv[t] = 1.f / tot;
    }
}

// ---------------- K6: normalize --------------------------------------------
__global__ void norm_kernel(float* __restrict__ out)
{
    int b = blockIdx.y;
    float inv = g_inv[b];
    int i = blockIdx.x * 256 + threadIdx.x;  // float4 index within row (12500 per row)
    if (i < 12500) {
        float4* p = reinterpret_cast<float4*>(out + (size_t)b * 50000);
        float4 v = p[i];
        v.x *= inv; v.y *= inv; v.z *= inv; v.w *= inv;
        p[i] = v;
    }
}

// ---------------- launch ----------------------------------------------------
extern "C" void kernel_launch(void* const* d_in, const int* in_sizes, int n_in,
                              void* d_out, int out_size)
{
    const float* E      = (const float*)d_in[0];
    const float* R      = (const float*)d_in[1];
    const float* U_root = (const float*)d_in[2];
    const float* U12    = (const float*)d_in[3];
    const float* U3R    = (const float*)d_in[4];
    const float* P      = (const float*)d_in[5];
    const float* gr     = (const float*)d_in[6];
    const float* br     = (const float*)d_in[7];
    const float* ge     = (const float*)d_in[8];
    const float* be     = (const float*)d_in[9];
    const float* gw     = (const float*)d_in[10];
    const float* bw     = (const float*)d_in[11];
    const int* r_idx    = (const int*)d_in[12];
    const int* e2_idx   = (const int*)d_in[13];
    const int* e3_idx   = (const int*)d_in[14];
    const int* miss     = (n_in > 15) ? (const int*)d_in[15] : nullptr;
    float* out = (float*)d_out;

    reduce_kernel<<<8192, 256>>>(U12, U3R);
    prep_kernel<<<1, 1024>>>(E, R, U_root, P, gr, br, ge, be, r_idx, e2_idx, e3_idx);
    contract_kernel<<<64, 256>>>(miss);
    logits_kernel<<<NBLK_LOG, 256>>>(E, gw, bw, out);
    suminv_kernel<<<1, 256>>>(NBLK_LOG);
    norm_kernel<<<dim3((12500 + 255) / 256, 64), 256>>>(out);
}